// round 16
// baseline (speedup 1.0000x reference)
#include <cuda_runtime.h>
#include <cuda_fp16.h>
#include <cstdint>

#define BB 4096
#define DD 256
#define UU 512

// ---------------- scratch (device globals: allocation-free rule) -------------
static __device__ __half g_xp[(size_t)BB * 5 * UU];           // 4096 x 2560 fp16
static __device__ __half g_rp[(size_t)BB * 3 * UU];           // 4096 x 1536 fp16

static __device__ __half g_xh[(size_t)BB * DD];               // A1 fp16
static __device__ __half g_hh[(size_t)BB * UU];               // A2 fp16
static __device__ __half g_wh[(size_t)DD * 5 * UU];           // B1 fp16
static __device__ __half g_rh[(size_t)UU * 3 * UU];           // B2 fp16

static __device__ int g_cnt[BB / 128];                        // per-row-block tile counter

// ---------------- PTX helpers ----------------
__device__ __forceinline__ uint32_t smem_u32(const void* p) {
    uint32_t a;
    asm("{ .reg .u64 t; cvta.to.shared.u64 t, %1; cvt.u32.u64 %0, t; }"
        : "=r"(a) : "l"(p));
    return a;
}
__device__ __forceinline__ void cp16(uint32_t saddr, const void* gaddr) {
    asm volatile("cp.async.cg.shared.global [%0], [%1], 16;"
                 :: "r"(saddr), "l"(gaddr) : "memory");
}
#define CP_COMMIT() asm volatile("cp.async.commit_group;" ::: "memory")
#define CP_WAIT(n)  asm volatile("cp.async.wait_group %0;" :: "n"(n) : "memory")

__device__ __forceinline__ void ldm_x4(uint32_t* r, uint32_t addr) {
    asm volatile("ldmatrix.sync.aligned.m8n8.x4.shared.b16 {%0,%1,%2,%3}, [%4];"
                 : "=r"(r[0]), "=r"(r[1]), "=r"(r[2]), "=r"(r[3]) : "r"(addr));
}
__device__ __forceinline__ void ldm_x4t(uint32_t* r, uint32_t addr) {
    asm volatile("ldmatrix.sync.aligned.m8n8.x4.trans.shared.b16 {%0,%1,%2,%3}, [%4];"
                 : "=r"(r[0]), "=r"(r[1]), "=r"(r[2]), "=r"(r[3]) : "r"(addr));
}
__device__ __forceinline__ void mma_f16(float* d, const uint32_t* a, const uint32_t* b) {
    asm volatile("mma.sync.aligned.m16n8k16.row.col.f32.f16.f16.f32 "
                 "{%0,%1,%2,%3}, {%4,%5,%6,%7}, {%8,%9}, {%0,%1,%2,%3};"
                 : "+f"(d[0]), "+f"(d[1]), "+f"(d[2]), "+f"(d[3])
                 : "r"(a[0]), "r"(a[1]), "r"(a[2]), "r"(a[3]), "r"(b[0]), "r"(b[1]));
}

// ---------------- fused vectorized fp32 -> fp16 convert (8 floats/thread) ----
#define NW0 (BB * DD / 8)
#define NW1 (NW0 + BB * UU / 8)
#define NW2 (NW1 + DD * 5 * UU / 8)
#define NW3 (NW2 + UU * 3 * UU / 8)

__global__ __launch_bounds__(256)
void split_all(const float* __restrict__ x, const float* __restrict__ h0,
               const float* __restrict__ w, const float* __restrict__ r,
               __half* __restrict__ xh, __half* __restrict__ hh,
               __half* __restrict__ wh, __half* __restrict__ rh) {
    // zero the per-row-block counters (stream-ordered before the GEMM launch)
    if (blockIdx.x == 0 && threadIdx.x < BB / 128) g_cnt[threadIdx.x] = 0;

    int i = blockIdx.x * 256 + threadIdx.x;          // vec8 index
    const float* src; __half* hi; int off;
    if (i < NW0)      { src = x;  hi = xh; off = i; }
    else if (i < NW1) { src = h0; hi = hh; off = i - NW0; }
    else if (i < NW2) { src = w;  hi = wh; off = i - NW1; }
    else              { src = r;  hi = rh; off = i - NW2; }

    float4 v0 = ((const float4*)src)[off * 2];
    float4 v1 = ((const float4*)src)[off * 2 + 1];
    __half2* hp = (__half2*)(hi) + off * 4;
    hp[0] = __half2(__float2half(v0.x), __float2half(v0.y));
    hp[1] = __half2(__float2half(v0.z), __float2half(v0.w));
    hp[2] = __half2(__float2half(v1.x), __float2half(v1.y));
    hp[3] = __half2(__float2half(v1.z), __float2half(v1.w));
}

// ---------------- elementwise LSTM math for one 128-row block ----------------
__device__ __forceinline__ float sigf(float x) { return 1.0f / (1.0f + __expf(-x)); }
__device__ __forceinline__ float tanhfast(float x) {
    float e = __expf(-2.0f * x);
    return __fdividef(1.0f - e, 1.0f + e);
}

struct F4v { float v[4]; };
__device__ __forceinline__ F4v ld4(const float* p) {
    float4 t = *(const float4*)p;
    F4v r; r.v[0] = t.x; r.v[1] = t.y; r.v[2] = t.z; r.v[3] = t.w;
    return r;
}
__device__ __forceinline__ F4v ld4h(const __half* p) {
    uint2 u = *(const uint2*)p;
    __half2 h0 = *(__half2*)&u.x;
    __half2 h1 = *(__half2*)&u.y;
    float2 f0 = __half22float2(h0);
    float2 f1 = __half22float2(h1);
    F4v r; r.v[0] = f0.x; r.v[1] = f0.y; r.v[2] = f1.x; r.v[3] = f1.y;
    return r;
}

__device__ __forceinline__
void eltwise_block(int bm, int tid,
                   const float* __restrict__ t, const float* __restrict__ c0,
                   const float* __restrict__ ktime, float* __restrict__ out) {
    // rows [bm*128, bm*128+128), 512 cols, 8 cols/item -> 8192 items / 256 thr
    for (int it = tid; it < 128 * UU / 8; it += 256) {
        const int b = bm * 128 + (it >> 6);
        const int u0 = (it & 63) << 3;
        const float tb = __ldg(&t[b]);

        #pragma unroll
        for (int half = 0; half < 2; half++) {
            const int u = u0 + half * 4;
            const __half* xp = g_xp + (size_t)b * (5 * UU) + u;
            const __half* rp = g_rp + (size_t)b * (3 * UU) + u;

            F4v xi  = ld4h(xp + 0 * UU);
            F4v xc  = ld4h(xp + 1 * UU);
            F4v xo  = ld4h(xp + 2 * UU);
            F4v xt1 = ld4h(xp + 3 * UU);
            F4v xt2 = ld4h(xp + 4 * UU);
            F4v ri  = ld4h(rp + 0 * UU);
            F4v rc  = ld4h(rp + 1 * UU);
            F4v ro  = ld4h(rp + 2 * UU);
            F4v c0v = ld4(c0 + (size_t)b * UU + u);
            F4v k1  = ld4(ktime + 0 * UU + u);
            F4v k2  = ld4(ktime + 1 * UU + u);
            F4v ko  = ld4(ktime + 2 * UU + u);

            float hv[4], cmv[4];
            #pragma unroll
            for (int j = 0; j < 4; j++) {
                float i_g = sigf(xi.v[j] + ri.v[j]);
                float t1  = sigf(xt1.v[j] + sigf(tb * k1.v[j]));
                float t1c = (t1 > -1e-5f) ? -1e-5f : t1;
                float t2  = sigf(xt2.v[j] + sigf(tb * k2.v[j]));
                float ct  = tanhfast(xc.v[j] + rc.v[j]);
                float cm_ = (1.0f - i_g * t1) * c0v.v[j] + i_g * ct * t1c;
                float cm  = (1.0f - i_g) * c0v.v[j] + i_g * ct * t2;
                float o   = sigf(xo.v[j] + ro.v[j] + tb * ko.v[j]);
                hv[j]  = tanhfast(cm_) * o;
                cmv[j] = cm;
            }

            float* hout = out + (size_t)b * UU + u;
            float* cout = out + (size_t)BB * UU + (size_t)b * UU + u;
            *(float4*)hout = make_float4(hv[0], hv[1], hv[2], hv[3]);
            *(float4*)cout = make_float4(cmv[0], cmv[1], cmv[2], cmv[3]);
        }
    }
}

// ---------------- HMMA GEMM tile: 128x128, single-phase fp16 (R13 config) ----
#define APAD 8
#define BPAD 8
#define A_ROWW (32 + APAD)          // half elems per A smem row (80 B)
#define B_ROWW (128 + BPAD)         // 272 B

#define A_BUF (128 * A_ROWW * 2)    // 10240 B
#define B_BUF (32 * B_ROWW * 2)     // 8704 B
#define STAGE_B (A_BUF + B_BUF)     // 18944 B
#define NSTAGE 4
#define SMEM_TOTAL (NSTAGE * STAGE_B)   // 75776 B

template<int K, int NTOT, int SEL>
__device__ __forceinline__
void gemm_tile(int bm, int bn, uint32_t sbase,
               const __half* __restrict__ A, const __half* __restrict__ Bh) {
    __half* __restrict__ C = (SEL == 0) ? g_xp : g_rp;

    const int tid = threadIdx.x;
    const int wid = tid >> 5, lane = tid & 31;
    const int wm = wid >> 2, wn = wid & 3;                 // 2 x 4 warp grid

    const int aRow = tid >> 2;          // 0..63 (+64)
    const int aSeg = tid & 3;
    const int bRow = tid >> 4;          // 0..15 (+16)
    const int bSeg = tid & 15;

    constexpr int KCH = K / 32;
    constexpr uint32_t A_ROW = A_ROWW * 2;                 // 80 B
    constexpr uint32_t B_ROW = B_ROWW * 2;                 // 272 B

    auto load_chunk = [&](int kk, int stage) {
        const uint32_t st = sbase + stage * STAGE_B;
        const __half* ag = A + (size_t)(bm * 128 + aRow) * K + kk * 32 + aSeg * 8;
        uint32_t sao = aRow * A_ROW + aSeg * 16;
        cp16(st + sao, ag);
        cp16(st + sao + 64 * A_ROW, ag + (size_t)64 * K);
        const __half* bg = Bh + (size_t)(kk * 32 + bRow) * NTOT + bn * 128 + bSeg * 8;
        uint32_t sb = st + A_BUF + bRow * B_ROW + bSeg * 16;
        cp16(sb, bg);
        cp16(sb + 16 * B_ROW, bg + (size_t)16 * NTOT);
        CP_COMMIT();
    };

    float acc[4][4][4];
    #pragma unroll
    for (int i = 0; i < 4; i++)
        #pragma unroll
        for (int j = 0; j < 4; j++)
            #pragma unroll
            for (int v = 0; v < 4; v++) acc[i][j][v] = 0.0f;

    load_chunk(0, 0);
    load_chunk(1, 1);
    load_chunk(2, 2);

    const int lrow = lane & 15;
    const int lhalf = lane >> 4;

    int stage = 0;
    for (int kc = 0; kc < KCH; ++kc) {
        if (kc <= KCH - 3)      { CP_WAIT(2); }
        else if (kc == KCH - 2) { CP_WAIT(1); }
        else                    { CP_WAIT(0); }
        __syncthreads();        // single barrier per chunk

        const uint32_t st = sbase + stage * STAGE_B;
        const uint32_t aBase = st;
        const uint32_t bBase = st + A_BUF;

        #pragma unroll
        for (int ks = 0; ks < 32; ks += 16) {
            uint32_t bfr[4][2];
            #pragma unroll
            for (int nh = 0; nh < 2; nh++) {
                uint32_t addr = bBase + (ks + lrow) * B_ROW
                              + (wn * 32 + nh * 16 + lhalf * 8) * 2;
                uint32_t r[4];
                ldm_x4t(r, addr);
                bfr[2 * nh][0] = r[0]; bfr[2 * nh][1] = r[1];
                bfr[2 * nh + 1][0] = r[2]; bfr[2 * nh + 1][1] = r[3];
            }
            uint32_t afr[4][4];
            #pragma unroll
            for (int mf = 0; mf < 4; mf++) {
                uint32_t addr = aBase + (wm * 64 + mf * 16 + lrow) * A_ROW
                              + (ks + lhalf * 8) * 2;
                ldm_x4(afr[mf], addr);
            }
            #pragma unroll
            for (int mf = 0; mf < 4; mf++)
                #pragma unroll
                for (int nf = 0; nf < 4; nf++)
                    mma_f16(acc[mf][nf], afr[mf], bfr[nf]);
        }

        if (kc + 3 < KCH) load_chunk(kc + 3, (kc + 3) & (NSTAGE - 1));

        stage = (stage + 1) & (NSTAGE - 1);
    }

    // epilogue: convert fp32 acc -> fp16, 4B half2 stores
    const int g = lane >> 2, q = lane & 3;
    #pragma unroll
    for (int mf = 0; mf < 4; mf++) {
        const int row0 = bm * 128 + wm * 64 + mf * 16 + g;
        #pragma unroll
        for (int nf = 0; nf < 4; nf++) {
            const int col = bn * 128 + wn * 32 + nf * 8 + q * 2;
            __half2 v0 = __floats2half2_rn(acc[mf][nf][0], acc[mf][nf][1]);
            __half2 v1 = __floats2half2_rn(acc[mf][nf][2], acc[mf][nf][3]);
            *(__half2*)(C + (size_t)row0 * NTOT + col)       = v0;
            *(__half2*)(C + (size_t)(row0 + 8) * NTOT + col) = v1;
        }
    }
}

// Merged launch + fused eltwise tail via per-row-block counters.
#define G2_TILES (3 * UU / 128 * (BB / 128))    // 384
#define G1_TILES (5 * UU / 128 * (BB / 128))    // 640
#define TILES_PER_BM (20 + 12)                  // 32 tiles complete a row block

__global__ __launch_bounds__(256, 2)
void hmma_both(const __half* __restrict__ xh, const __half* __restrict__ wh,
               const __half* __restrict__ hh, const __half* __restrict__ rh,
               const float* __restrict__ t, const float* __restrict__ c0,
               const float* __restrict__ ktime, float* __restrict__ out) {
    extern __shared__ __align__(16) char dynsmem[];
    const uint32_t sbase = smem_u32(dynsmem);

    const int bid = blockIdx.x;
    int bm;
    if (bid < G2_TILES) {
        bm = bid / 12;
        const int bn = bid % 12;
        gemm_tile<UU, 3 * UU, 1>(bm, bn, sbase, hh, rh);
    } else {
        const int b1 = bid - G2_TILES;
        bm = b1 / 20;
        const int bn = b1 % 20;
        gemm_tile<DD, 5 * UU, 0>(bm, bn, sbase, xh, wh);
    }

    // completion counting: make tile stores visible, then count this tile.
    __syncthreads();                       // all threads' stores issued
    __threadfence();                       // visible device-wide
    __shared__ int s_old;
    if (threadIdx.x == 0) s_old = atomicAdd(&g_cnt[bm], 1);
    __syncthreads();

    if (s_old == TILES_PER_BM - 1) {
        // last tile of this 128-row block: all 32 tiles' data visible
        // (each was fenced before its atomic). Run its eltwise here.
        __threadfence();                   // order counter read before data reads
        eltwise_block(bm, threadIdx.x, t, c0, ktime, out);
    }
}

// ---------------- launch ----------------
extern "C" void kernel_launch(void* const* d_in, const int* in_sizes, int n_in,
                              void* d_out, int out_size) {
    const float* x     = (const float*)d_in[0];
    const float* t     = (const float*)d_in[1];
    const float* h0    = (const float*)d_in[2];
    const float* c0    = (const float*)d_in[3];
    const float* kern  = (const float*)d_in[4];
    const float* rkern = (const float*)d_in[5];
    const float* ktime = (const float*)d_in[6];
    float* out = (float*)d_out;

    __half *xh, *hh, *wh, *rh;
    cudaGetSymbolAddress((void**)&xh, g_xh);
    cudaGetSymbolAddress((void**)&hh, g_hh);
    cudaGetSymbolAddress((void**)&wh, g_wh);
    cudaGetSymbolAddress((void**)&rh, g_rh);

    cudaFuncSetAttribute(hmma_both,
                         cudaFuncAttributeMaxDynamicSharedMemorySize, SMEM_TOTAL);

    split_all<<<NW3 / 256, 256>>>(x, h0, kern, rkern, xh, hh, wh, rh);

    hmma_both<<<G1_TILES + G2_TILES, 256, SMEM_TOTAL>>>(xh, wh, hh, rh,
                                                        t, c0, ktime, out);
}

// round 17
// speedup vs baseline: 2.9401x; 2.9401x over previous
#include <cuda_runtime.h>
#include <cuda_fp16.h>
#include <cstdint>

#define BB 4096
#define DD 256
#define UU 512

// ---------------- scratch (device globals: allocation-free rule) -------------
static __device__ __half g_xp[(size_t)BB * 5 * UU];           // 4096 x 2560 fp16
static __device__ __half g_rp[(size_t)BB * 3 * UU];           // 4096 x 1536 fp16

static __device__ __half g_xh[(size_t)BB * DD];               // A1 fp16
static __device__ __half g_hh[(size_t)BB * UU];               // A2 fp16
static __device__ __half g_wh[(size_t)DD * 5 * UU];           // B1 fp16
static __device__ __half g_rh[(size_t)UU * 3 * UU];           // B2 fp16

// ---------------- PTX helpers ----------------
__device__ __forceinline__ uint32_t smem_u32(const void* p) {
    uint32_t a;
    asm("{ .reg .u64 t; cvta.to.shared.u64 t, %1; cvt.u32.u64 %0, t; }"
        : "=r"(a) : "l"(p));
    return a;
}
__device__ __forceinline__ void cp16(uint32_t saddr, const void* gaddr) {
    asm volatile("cp.async.cg.shared.global [%0], [%1], 16;"
                 :: "r"(saddr), "l"(gaddr) : "memory");
}
#define CP_COMMIT() asm volatile("cp.async.commit_group;" ::: "memory")
#define CP_WAIT(n)  asm volatile("cp.async.wait_group %0;" :: "n"(n) : "memory")

__device__ __forceinline__ void ldm_x4(uint32_t* r, uint32_t addr) {
    asm volatile("ldmatrix.sync.aligned.m8n8.x4.shared.b16 {%0,%1,%2,%3}, [%4];"
                 : "=r"(r[0]), "=r"(r[1]), "=r"(r[2]), "=r"(r[3]) : "r"(addr));
}
__device__ __forceinline__ void ldm_x4t(uint32_t* r, uint32_t addr) {
    asm volatile("ldmatrix.sync.aligned.m8n8.x4.trans.shared.b16 {%0,%1,%2,%3}, [%4];"
                 : "=r"(r[0]), "=r"(r[1]), "=r"(r[2]), "=r"(r[3]) : "r"(addr));
}
__device__ __forceinline__ void mma_f16(float* d, const uint32_t* a, const uint32_t* b) {
    asm volatile("mma.sync.aligned.m16n8k16.row.col.f32.f16.f16.f32 "
                 "{%0,%1,%2,%3}, {%4,%5,%6,%7}, {%8,%9}, {%0,%1,%2,%3};"
                 : "+f"(d[0]), "+f"(d[1]), "+f"(d[2]), "+f"(d[3])
                 : "r"(a[0]), "r"(a[1]), "r"(a[2]), "r"(a[3]), "r"(b[0]), "r"(b[1]));
}

// ---------------- fused vectorized fp32 -> fp16 convert ----------------------
#define NV0 (BB * DD / 4)
#define NV1 (NV0 + BB * UU / 4)
#define NV2 (NV1 + DD * 5 * UU / 4)
#define NV3 (NV2 + UU * 3 * UU / 4)

__global__ __launch_bounds__(256)
void split_all(const float* __restrict__ x, const float* __restrict__ h0,
               const float* __restrict__ w, const float* __restrict__ r,
               __half* __restrict__ xh, __half* __restrict__ hh,
               __half* __restrict__ wh, __half* __restrict__ rh) {
    int i = blockIdx.x * 256 + threadIdx.x;          // vec4 index
    const float* src; __half* hi; int off;
    if (i < NV0)      { src = x;  hi = xh; off = i; }
    else if (i < NV1) { src = h0; hi = hh; off = i - NV0; }
    else if (i < NV2) { src = w;  hi = wh; off = i - NV1; }
    else              { src = r;  hi = rh; off = i - NV2; }

    float4 v = ((const float4*)src)[off];
    __half2* hp = (__half2*)(hi) + off * 2;
    hp[0] = __half2(__float2half(v.x), __float2half(v.y));
    hp[1] = __half2(__float2half(v.z), __float2half(v.w));
}

// ---------------- HMMA GEMM tile: 128x128, single-phase fp16 -----------------
// 4-stage cp.async pipeline, ONE __syncthreads per K-chunk, 2 CTAs/SM.
// fp16 output (feeds sigmoid/tanh epilogue only).
#define APAD 8
#define BPAD 8
#define A_ROWW (32 + APAD)          // half elems per A smem row (80 B)
#define B_ROWW (128 + BPAD)         // 272 B

#define A_BUF (128 * A_ROWW * 2)    // 10240 B
#define B_BUF (32 * B_ROWW * 2)     // 8704 B
#define STAGE_B (A_BUF + B_BUF)     // 18944 B
#define NSTAGE 4
#define SMEM_TOTAL (NSTAGE * STAGE_B)   // 75776 B

template<int K, int NTOT, int SEL>
__device__ __forceinline__
void gemm_tile(int bm, int bn, uint32_t sbase,
               const __half* __restrict__ A, const __half* __restrict__ Bh) {
    __half* __restrict__ C = (SEL == 0) ? g_xp : g_rp;

    const int tid = threadIdx.x;
    const int wid = tid >> 5, lane = tid & 31;
    const int wm = wid >> 2, wn = wid & 3;                 // 2 x 4 warp grid

    const int aRow = tid >> 2;          // 0..63 (+64)
    const int aSeg = tid & 3;
    const int bRow = tid >> 4;          // 0..15 (+16)
    const int bSeg = tid & 15;

    constexpr int KCH = K / 32;
    constexpr uint32_t A_ROW = A_ROWW * 2;                 // 80 B
    constexpr uint32_t B_ROW = B_ROWW * 2;                 // 272 B

    auto load_chunk = [&](int kk, int stage) {
        const uint32_t st = sbase + stage * STAGE_B;
        const __half* ag = A + (size_t)(bm * 128 + aRow) * K + kk * 32 + aSeg * 8;
        uint32_t sao = aRow * A_ROW + aSeg * 16;
        cp16(st + sao, ag);
        cp16(st + sao + 64 * A_ROW, ag + (size_t)64 * K);
        const __half* bg = Bh + (size_t)(kk * 32 + bRow) * NTOT + bn * 128 + bSeg * 8;
        uint32_t sb = st + A_BUF + bRow * B_ROW + bSeg * 16;
        cp16(sb, bg);
        cp16(sb + 16 * B_ROW, bg + (size_t)16 * NTOT);
        CP_COMMIT();
    };

    float acc[4][4][4];
    #pragma unroll
    for (int i = 0; i < 4; i++)
        #pragma unroll
        for (int j = 0; j < 4; j++)
            #pragma unroll
            for (int v = 0; v < 4; v++) acc[i][j][v] = 0.0f;

    load_chunk(0, 0);
    load_chunk(1, 1);
    load_chunk(2, 2);

    const int lrow = lane & 15;
    const int lhalf = lane >> 4;

    int stage = 0;             // stage holding chunk kc
    for (int kc = 0; kc < KCH; ++kc) {
        if (kc <= KCH - 3)      { CP_WAIT(2); }
        else if (kc == KCH - 2) { CP_WAIT(1); }
        else                    { CP_WAIT(0); }
        __syncthreads();        // single barrier per chunk

        const uint32_t st = sbase + stage * STAGE_B;
        const uint32_t aBase = st;
        const uint32_t bBase = st + A_BUF;

        #pragma unroll
        for (int ks = 0; ks < 32; ks += 16) {
            uint32_t bfr[4][2];
            #pragma unroll
            for (int nh = 0; nh < 2; nh++) {
                uint32_t addr = bBase + (ks + lrow) * B_ROW
                              + (wn * 32 + nh * 16 + lhalf * 8) * 2;
                uint32_t r[4];
                ldm_x4t(r, addr);
                bfr[2 * nh][0] = r[0]; bfr[2 * nh][1] = r[1];
                bfr[2 * nh + 1][0] = r[2]; bfr[2 * nh + 1][1] = r[3];
            }
            uint32_t afr[4][4];
            #pragma unroll
            for (int mf = 0; mf < 4; mf++) {
                uint32_t addr = aBase + (wm * 64 + mf * 16 + lrow) * A_ROW
                              + (ks + lhalf * 8) * 2;
                ldm_x4(afr[mf], addr);
            }
            #pragma unroll
            for (int mf = 0; mf < 4; mf++)
                #pragma unroll
                for (int nf = 0; nf < 4; nf++)
                    mma_f16(acc[mf][nf], afr[mf], bfr[nf]);
        }

        if (kc + 3 < KCH) load_chunk(kc + 3, (kc + 3) & (NSTAGE - 1));

        stage = (stage + 1) & (NSTAGE - 1);
    }

    // epilogue: convert fp32 acc -> fp16, 4B half2 stores
    const int g = lane >> 2, q = lane & 3;
    #pragma unroll
    for (int mf = 0; mf < 4; mf++) {
        const int row0 = bm * 128 + wm * 64 + mf * 16 + g;
        #pragma unroll
        for (int nf = 0; nf < 4; nf++) {
            const int col = bn * 128 + wn * 32 + nf * 8 + q * 2;
            __half2 v0 = __floats2half2_rn(acc[mf][nf][0], acc[mf][nf][1]);
            __half2 v1 = __floats2half2_rn(acc[mf][nf][2], acc[mf][nf][3]);
            *(__half2*)(C + (size_t)row0 * NTOT + col)       = v0;
            *(__half2*)(C + (size_t)(row0 + 8) * NTOT + col) = v1;
        }
    }
}

// Merged launch: GEMM2 tiles (K=512, longer) first for LPT packing.
#define G2_TILES (3 * UU / 128 * (BB / 128))    // 384
#define G1_TILES (5 * UU / 128 * (BB / 128))    // 640

__global__ __launch_bounds__(256, 2)
void hmma_both(const __half* __restrict__ xh, const __half* __restrict__ wh,
               const __half* __restrict__ hh, const __half* __restrict__ rh) {
    extern __shared__ __align__(16) char dynsmem[];
    const uint32_t sbase = smem_u32(dynsmem);

    const int bid = blockIdx.x;
    if (bid < G2_TILES) {
        const int bm = bid / 12, bn = bid % 12;
        gemm_tile<UU, 3 * UU, 1>(bm, bn, sbase, hh, rh);
    } else {
        const int b1 = bid - G2_TILES;
        const int bm = b1 / 20, bn = b1 % 20;
        gemm_tile<DD, 5 * UU, 0>(bm, bn, sbase, xh, wh);
    }
}

// ---------------- fused elementwise LSTM epilogue ----------------
__device__ __forceinline__ float sigf(float x) { return 1.0f / (1.0f + __expf(-x)); }

struct F4v { float v[4]; };
__device__ __forceinline__ F4v ld4(const float* p) {
    float4 t = *(const float4*)p;
    F4v r; r.v[0] = t.x; r.v[1] = t.y; r.v[2] = t.z; r.v[3] = t.w;
    return r;
}
// load 4 halves (8B) -> 4 floats
__device__ __forceinline__ F4v ld4h(const __half* p) {
    uint2 u = *(const uint2*)p;
    __half2 h0 = *(__half2*)&u.x;
    __half2 h1 = *(__half2*)&u.y;
    float2 f0 = __half22float2(h0);
    float2 f1 = __half22float2(h1);
    F4v r; r.v[0] = f0.x; r.v[1] = f0.y; r.v[2] = f1.x; r.v[3] = f1.y;
    return r;
}

__global__ __launch_bounds__(256)
void eltwise(const float* __restrict__ t, const float* __restrict__ c0,
             const float* __restrict__ ktime, float* __restrict__ out) {
    int idx = blockIdx.x * 256 + threadIdx.x;
    int b = idx >> 7;
    int u = (idx & 127) << 2;

    const float tb = __ldg(&t[b]);
    const __half* xp = g_xp + (size_t)b * (5 * UU) + u;
    const __half* rp = g_rp + (size_t)b * (3 * UU) + u;

    F4v xi  = ld4h(xp + 0 * UU);
    F4v xc  = ld4h(xp + 1 * UU);
    F4v xo  = ld4h(xp + 2 * UU);
    F4v xt1 = ld4h(xp + 3 * UU);
    F4v xt2 = ld4h(xp + 4 * UU);
    F4v ri  = ld4h(rp + 0 * UU);
    F4v rc  = ld4h(rp + 1 * UU);
    F4v ro  = ld4h(rp + 2 * UU);
    F4v c0v = ld4(c0 + (size_t)b * UU + u);
    F4v k1  = ld4(ktime + 0 * UU + u);
    F4v k2  = ld4(ktime + 1 * UU + u);
    F4v ko  = ld4(ktime + 2 * UU + u);

    float hv[4], cmv[4];
    #pragma unroll
    for (int j = 0; j < 4; j++) {
        float i_g = sigf(xi.v[j] + ri.v[j]);
        float t1  = sigf(xt1.v[j] + sigf(tb * k1.v[j]));
        float t1c = (t1 > -1e-5f) ? -1e-5f : t1;
        float t2  = sigf(xt2.v[j] + sigf(tb * k2.v[j]));
        float ct  = tanhf(xc.v[j] + rc.v[j]);
        float cm_ = (1.0f - i_g * t1) * c0v.v[j] + i_g * ct * t1c;
        float cm  = (1.0f - i_g) * c0v.v[j] + i_g * ct * t2;
        float o   = sigf(xo.v[j] + ro.v[j] + tb * ko.v[j]);
        hv[j]  = tanhf(cm_) * o;
        cmv[j] = cm;
    }

    float* hout = out + (size_t)b * UU + u;
    float* cout = out + (size_t)BB * UU + (size_t)b * UU + u;
    *(float4*)hout = make_float4(hv[0], hv[1], hv[2], hv[3]);
    *(float4*)cout = make_float4(cmv[0], cmv[1], cmv[2], cmv[3]);
}

// ---------------- launch ----------------
extern "C" void kernel_launch(void* const* d_in, const int* in_sizes, int n_in,
                              void* d_out, int out_size) {
    const float* x     = (const float*)d_in[0];
    const float* t     = (const float*)d_in[1];
    const float* h0    = (const float*)d_in[2];
    const float* c0    = (const float*)d_in[3];
    const float* kern  = (const float*)d_in[4];
    const float* rkern = (const float*)d_in[5];
    const float* ktime = (const float*)d_in[6];
    float* out = (float*)d_out;

    __half *xh, *hh, *wh, *rh;
    cudaGetSymbolAddress((void**)&xh, g_xh);
    cudaGetSymbolAddress((void**)&hh, g_hh);
    cudaGetSymbolAddress((void**)&wh, g_wh);
    cudaGetSymbolAddress((void**)&rh, g_rh);

    cudaFuncSetAttribute(hmma_both,
                         cudaFuncAttributeMaxDynamicSharedMemorySize, SMEM_TOTAL);

    split_all<<<NV3 / 256, 256>>>(x, h0, kern, rkern, xh, hh, wh, rh);

    hmma_both<<<G1_TILES + G2_TILES, 256, SMEM_TOTAL>>>(xh, wh, hh, rh);

    eltwise<<<(BB * UU / 4) / 256, 256>>>(t, c0, ktime, out);
}